// round 2
// baseline (speedup 1.0000x reference)
#include <cuda_runtime.h>
#include <cuda_bf16.h>
#include <math.h>

// Shapes (fixed by the problem)
#define NB   16
#define CCH  256
#define HH   32
#define WW   32
#define LL   (HH*WW)       // 1024
#define PP   2048
#define KEEP 102           // int(0.05 * 2048)

// Scratch (device globals only; no allocations allowed)
__device__ float g_poolN[PP * CCH];        // 2 MB  : pool rows / ||pool_p||
__device__ float g_invxn[NB * LL];         // 64 KB : 1/||x_{n,l}||
__device__ float g_cos[(size_t)NB * LL * PP]; // 134 MB : cos[n][l][p]

// ---------------------------------------------------------------------------
// Kernel 1: row-normalize pool. One block per pool row, 256 threads.
// ---------------------------------------------------------------------------
__global__ void prep_pool(const float* __restrict__ pool) {
    int p = blockIdx.x;
    int c = threadIdx.x;
    float v = pool[p * CCH + c];
    __shared__ float red[256];
    red[c] = v * v;
    __syncthreads();
    #pragma unroll
    for (int s = 128; s > 0; s >>= 1) {
        if (c < s) red[c] += red[c + s];
        __syncthreads();
    }
    float inv = 1.0f / sqrtf(red[0]);
    g_poolN[p * CCH + c] = v * inv;
}

// ---------------------------------------------------------------------------
// Kernel 2: per-pixel inverse norm of x. One thread per (n,l); coalesced in l.
// ---------------------------------------------------------------------------
__global__ void prep_xnorm(const float* __restrict__ x) {
    int idx = blockIdx.x * 256 + threadIdx.x;   // 0 .. 16383
    int n = idx >> 10, l = idx & (LL - 1);
    const float* xp = x + (size_t)n * CCH * LL + l;
    float s = 0.f;
    #pragma unroll 8
    for (int c = 0; c < CCH; c++) {
        float v = xp[c * LL];
        s = fmaf(v, v, s);
    }
    g_invxn[idx] = 1.0f / sqrtf(s);
}

// ---------------------------------------------------------------------------
// Kernel 3: cos[n][l][p] = sum_c poolN[p][c] * x[n][c][l] * invxn[n][l]
// SGEMM: M = L (rows, pixels), N = P (cols), K = C = 256.
// Block tile 128x128, K-tile 16, 256 threads, 8x8 per thread.
// ---------------------------------------------------------------------------
#define BM 128
#define BN 128
#define BK 16
#define TM 8
#define TN 8

__global__ __launch_bounds__(256) void gemm_cos(const float* __restrict__ x) {
    int n    = blockIdx.z;
    int pBlk = blockIdx.x * BN;
    int lBlk = blockIdx.y * BM;
    const float* xA = x + (size_t)n * CCH * LL;

    __shared__ float As[BK][BM];
    __shared__ float Bs[BK][BN];

    int tid = threadIdx.x;
    int tr = tid >> 4;        // 0..15 (row group of 8 pixels)
    int tc = tid & 15;        // 0..15 (col group of 8 pool entries)

    // A loader: As[k][l]; thread covers (k = tid>>5 [+8], l4 = (tid&31)*4)
    int la_k = tid >> 5;
    int la_l = (tid & 31) << 2;
    // B loader: thread covers row p = tid&127, k-quad g = tid>>7 [+2]
    int lb_p = tid & 127;
    int lb_g = tid >> 7;

    float acc[TM][TN] = {};

    for (int k0 = 0; k0 < CCH; k0 += BK) {
        #pragma unroll
        for (int kk = 0; kk < 2; kk++) {
            int k = la_k + kk * 8;
            float4 v = *(const float4*)&xA[(size_t)(k0 + k) * LL + lBlk + la_l];
            *(float4*)&As[k][la_l] = v;
        }
        #pragma unroll
        for (int gg = 0; gg < 2; gg++) {
            int g = lb_g + gg * 2;  // 0..3
            float4 v = *(const float4*)&g_poolN[(size_t)(pBlk + lb_p) * CCH + k0 + g * 4];
            Bs[g * 4 + 0][lb_p] = v.x;
            Bs[g * 4 + 1][lb_p] = v.y;
            Bs[g * 4 + 2][lb_p] = v.z;
            Bs[g * 4 + 3][lb_p] = v.w;
        }
        __syncthreads();

        #pragma unroll
        for (int k = 0; k < BK; k++) {
            float ra[TM], rb[TN];
            #pragma unroll
            for (int i = 0; i < TM; i++) ra[i] = As[k][tr * TM + i];
            #pragma unroll
            for (int j = 0; j < TN; j++) rb[j] = Bs[k][tc * TN + j];
            #pragma unroll
            for (int i = 0; i < TM; i++)
                #pragma unroll
                for (int j = 0; j < TN; j++)
                    acc[i][j] = fmaf(ra[i], rb[j], acc[i][j]);
        }
        __syncthreads();
    }

    float* outn = g_cos + (size_t)n * LL * PP;
    #pragma unroll
    for (int i = 0; i < TM; i++) {
        int l = lBlk + tr * TM + i;
        float s = g_invxn[n * LL + l];
        #pragma unroll
        for (int j = 0; j < TN; j += 4) {
            float4 v;
            v.x = acc[i][j + 0] * s;
            v.y = acc[i][j + 1] * s;
            v.z = acc[i][j + 2] * s;
            v.w = acc[i][j + 3] * s;
            *(float4*)&outn[(size_t)l * PP + pBlk + tc * TN + j] = v;
        }
    }
}

// ---------------------------------------------------------------------------
// Kernel 4: per-pixel exact top-102 radix select (by |cos|) + sparse recon.
// One block per (n,l), 256 threads (one per channel for the gather phase).
// ---------------------------------------------------------------------------
__global__ __launch_bounds__(256) void topk_recon(const float* __restrict__ pool,
                                                  float* __restrict__ out) {
    int blk = blockIdx.x;            // n*1024 + l
    int n = blk >> 10, l = blk & (LL - 1);
    const float* row = g_cos + (size_t)blk * PP;

    __shared__ float    sv[PP];
    __shared__ unsigned hist[256];
    __shared__ unsigned s_prefix;
    __shared__ int      s_k, s_cnt, s_eq;
    __shared__ int      s_idx[KEEP];
    __shared__ float    s_val[KEEP];
    __shared__ float    s_invS;

    int tid = threadIdx.x;

    // load the full cos row (8 KB) into shared
    #pragma unroll
    for (int j = 0; j < 2; j++) {
        int i = (tid + j * 256) * 4;
        *(float4*)&sv[i] = *(const float4*)&row[i];
    }
    if (tid == 0) { s_prefix = 0u; s_k = KEEP; s_cnt = 0; s_eq = 0; }
    __syncthreads();

    // 4-level MSB radix select on abs-value bit patterns (positive floats are
    // monotone as uints). After the loop: s_prefix == exact 102nd-largest key,
    // s_k == number of ties at that key that must be included.
    for (int level = 0; level < 4; level++) {
        int shift = 24 - level * 8;
        hist[tid] = 0;
        __syncthreads();
        unsigned pref = s_prefix;
        unsigned maskHigh = (level == 0) ? 0u : (0xFFFFFFFFu << (shift + 8));
        #pragma unroll
        for (int j = 0; j < 8; j++) {
            unsigned key = __float_as_uint(fabsf(sv[tid * 8 + j]));
            if ((key & maskHigh) == pref)
                atomicAdd(&hist[(key >> shift) & 0xFF], 1u);
        }
        __syncthreads();
        if (tid == 0) {
            int k = s_k;
            unsigned cum = 0;
            int b = 255;
            for (; b >= 0; b--) {
                cum += hist[b];
                if ((int)cum >= k) break;
            }
            s_k = k - (int)(cum - hist[b]);
            s_prefix = pref | ((unsigned)b << shift);
        }
        __syncthreads();
    }

    unsigned T = s_prefix;
    int need = s_k;

    // Collect exactly KEEP entries: all keys > T, plus `need` ties at == T.
    #pragma unroll
    for (int j = 0; j < 8; j++) {
        int i = tid * 8 + j;
        float v = sv[i];
        unsigned key = __float_as_uint(fabsf(v));
        if (key > T) {
            int slot = atomicAdd(&s_cnt, 1);
            s_idx[slot] = i;
            s_val[slot] = v;
        } else if (key == T) {
            int t = atomicAdd(&s_eq, 1);
            if (t < need) {
                int slot = atomicAdd(&s_cnt, 1);
                s_idx[slot] = i;
                s_val[slot] = v;
            }
        }
    }
    __syncthreads();

    if (tid == 0) {
        float S = 0.f;
        for (int i = 0; i < KEEP; i++) S += s_val[i];
        s_invS = 1.0f / S;
    }
    __syncthreads();

    // Sparse reconstruction: each thread owns channel c = tid.
    // pool (2 MB) stays L2-resident; reads are broadcast-indexed + coalesced.
    float acc = 0.f;
    #pragma unroll 6
    for (int j = 0; j < KEEP; j++) {
        acc = fmaf(s_val[j], __ldg(&pool[(size_t)s_idx[j] * CCH + tid]), acc);
    }
    out[(size_t)n * CCH * LL + (size_t)tid * LL + l] = acc * s_invS;
}

// ---------------------------------------------------------------------------
// Launch
// ---------------------------------------------------------------------------
extern "C" void kernel_launch(void* const* d_in, const int* in_sizes, int n_in,
                              void* d_out, int out_size) {
    const float* x    = (const float*)d_in[0];  // [16, 256, 32, 32]
    const float* pool = (const float*)d_in[1];  // [2048, 256]
    float* out        = (float*)d_out;          // [16, 256, 32, 32]

    prep_pool<<<PP, 256>>>(pool);
    prep_xnorm<<<(NB * LL) / 256, 256>>>(x);
    gemm_cos<<<dim3(PP / BN, LL / BM, NB), 256>>>(x);
    topk_recon<<<NB * LL, 256>>>(pool, out);
}

// round 3
// speedup vs baseline: 1.1709x; 1.1709x over previous
#include <cuda_runtime.h>
#include <cuda_bf16.h>
#include <math.h>

// Shapes (fixed by the problem)
#define NB   16
#define CCH  256
#define HH   32
#define WW   32
#define LL   (HH*WW)       // 1024
#define PP   2048
#define KEEP 102           // int(0.05 * 2048)

// Scratch (device globals only; no allocations allowed)
__device__ float g_poolN[PP * CCH];           // 2 MB  : pool rows / ||pool_p||
__device__ float g_invxn[NB * LL];            // 64 KB : 1/||x_{n,l}||
__device__ float g_cos[(size_t)NB * LL * PP]; // 134 MB : cos[n][l][p]

// ---------------------------------------------------------------------------
// Kernel 1: row-normalize pool. One block per pool row, 256 threads.
// ---------------------------------------------------------------------------
__global__ void prep_pool(const float* __restrict__ pool) {
    int p = blockIdx.x;
    int c = threadIdx.x;
    float v = pool[p * CCH + c];
    __shared__ float red[256];
    red[c] = v * v;
    __syncthreads();
    #pragma unroll
    for (int s = 128; s > 0; s >>= 1) {
        if (c < s) red[c] += red[c + s];
        __syncthreads();
    }
    float inv = 1.0f / sqrtf(red[0]);
    g_poolN[p * CCH + c] = v * inv;
}

// ---------------------------------------------------------------------------
// Kernel 2: per-pixel inverse norm of x. One thread per (n,l); coalesced in l.
// ---------------------------------------------------------------------------
__global__ void prep_xnorm(const float* __restrict__ x) {
    int idx = blockIdx.x * 256 + threadIdx.x;   // 0 .. 16383
    int n = idx >> 10, l = idx & (LL - 1);
    const float* xp = x + (size_t)n * CCH * LL + l;
    float s = 0.f;
    #pragma unroll 8
    for (int c = 0; c < CCH; c++) {
        float v = xp[c * LL];
        s = fmaf(v, v, s);
    }
    g_invxn[idx] = 1.0f / sqrtf(s);
}

// ---------------------------------------------------------------------------
// Kernel 3: cos[n][l][p] = sum_c poolN[p][c] * x[n][c][l] * invxn[n][l]
// SGEMM: M = L, N = P, K = 256. 128x128 tile, BK=16, 256 threads, 8x8/thread.
// (~CUDA-core fp32 peak already; tcgen05 rewrite is a future round.)
// ---------------------------------------------------------------------------
#define BM 128
#define BN 128
#define BK 16
#define TM 8
#define TN 8

__global__ __launch_bounds__(256) void gemm_cos(const float* __restrict__ x) {
    int n    = blockIdx.z;
    int pBlk = blockIdx.x * BN;
    int lBlk = blockIdx.y * BM;
    const float* xA = x + (size_t)n * CCH * LL;

    __shared__ float As[BK][BM];
    __shared__ float Bs[BK][BN];

    int tid = threadIdx.x;
    int tr = tid >> 4;
    int tc = tid & 15;

    int la_k = tid >> 5;
    int la_l = (tid & 31) << 2;
    int lb_p = tid & 127;
    int lb_g = tid >> 7;

    float acc[TM][TN] = {};

    for (int k0 = 0; k0 < CCH; k0 += BK) {
        #pragma unroll
        for (int kk = 0; kk < 2; kk++) {
            int k = la_k + kk * 8;
            float4 v = *(const float4*)&xA[(size_t)(k0 + k) * LL + lBlk + la_l];
            *(float4*)&As[k][la_l] = v;
        }
        #pragma unroll
        for (int gg = 0; gg < 2; gg++) {
            int g = lb_g + gg * 2;
            float4 v = *(const float4*)&g_poolN[(size_t)(pBlk + lb_p) * CCH + k0 + g * 4];
            Bs[g * 4 + 0][lb_p] = v.x;
            Bs[g * 4 + 1][lb_p] = v.y;
            Bs[g * 4 + 2][lb_p] = v.z;
            Bs[g * 4 + 3][lb_p] = v.w;
        }
        __syncthreads();

        #pragma unroll
        for (int k = 0; k < BK; k++) {
            float ra[TM], rb[TN];
            #pragma unroll
            for (int i = 0; i < TM; i++) ra[i] = As[k][tr * TM + i];
            #pragma unroll
            for (int j = 0; j < TN; j++) rb[j] = Bs[k][tc * TN + j];
            #pragma unroll
            for (int i = 0; i < TM; i++)
                #pragma unroll
                for (int j = 0; j < TN; j++)
                    acc[i][j] = fmaf(ra[i], rb[j], acc[i][j]);
        }
        __syncthreads();
    }

    float* outn = g_cos + (size_t)n * LL * PP;
    #pragma unroll
    for (int i = 0; i < TM; i++) {
        int l = lBlk + tr * TM + i;
        float s = g_invxn[n * LL + l];
        #pragma unroll
        for (int j = 0; j < TN; j += 4) {
            float4 v;
            v.x = acc[i][j + 0] * s;
            v.y = acc[i][j + 1] * s;
            v.z = acc[i][j + 2] * s;
            v.w = acc[i][j + 3] * s;
            *(float4*)&outn[(size_t)l * PP + pBlk + tc * TN + j] = v;
        }
    }
}

// ---------------------------------------------------------------------------
// Kernel 4: per-pixel exact top-102 via ATOMIC-FREE binary search on |cos|
// bit pattern, then sparse reconstruction. One block per (n,l), 256 threads.
//
// Selection: find T = exact 102nd-largest key by binary search on the
// positive-float value (float compare == integer-pattern compare for
// non-negative floats). Per step: 8 register compares per thread,
// __reduce_add_sync, one lane0 atomicAdd to a fresh counter slot, one
// barrier. No contended histogram atomics, no shared re-sweeps.
// ---------------------------------------------------------------------------
#define NIT 30   // search range [0, 0x3FC00000) = |cos| in [0, 1.5); 2^30 span

__global__ __launch_bounds__(256) void topk_recon(const float* __restrict__ pool,
                                                  float* __restrict__ out) {
    int blk = blockIdx.x;            // n*1024 + l
    int n = blk >> 10, l = blk & (LL - 1);
    const float* row = g_cos + (size_t)blk * PP;

    __shared__ float sv[PP];         // signed cos row (for collection/gather)
    __shared__ int   cnt[NIT + 2];   // one counter per search step (+1 for c1)
    __shared__ int   s_cnt, s_eq;
    __shared__ int   s_idx[KEEP];
    __shared__ float s_val[KEEP];
    __shared__ float s_invS;

    int tid = threadIdx.x;

    // Load 8 floats/thread (two coalesced float4), mirror to shared.
    float4 r0 = *(const float4*)&row[tid * 4];
    float4 r1 = *(const float4*)&row[1024 + tid * 4];
    *(float4*)&sv[tid * 4]        = r0;
    *(float4*)&sv[1024 + tid * 4] = r1;

    // Register-resident |keys|
    float a0 = fabsf(r0.x), a1 = fabsf(r0.y), a2 = fabsf(r0.z), a3 = fabsf(r0.w);
    float a4 = fabsf(r1.x), a5 = fabsf(r1.y), a6 = fabsf(r1.z), a7 = fabsf(r1.w);

    if (tid < NIT + 2) cnt[tid] = 0;
    if (tid == 0) { s_cnt = 0; s_eq = 0; }
    __syncthreads();

    // Binary search: largest t with #{key >= t} >= KEEP  ==> t is the exact
    // 102nd-largest key present.
    unsigned lo = 0u, hi = 0x3FC00000u;
    #pragma unroll 1
    for (int it = 0; it < NIT; it++) {
        unsigned mid = (lo + hi) >> 1;
        float mf = __uint_as_float(mid);
        int c = (a0 >= mf) + (a1 >= mf) + (a2 >= mf) + (a3 >= mf)
              + (a4 >= mf) + (a5 >= mf) + (a6 >= mf) + (a7 >= mf);
        c = __reduce_add_sync(0xFFFFFFFFu, c);
        if ((tid & 31) == 0) atomicAdd(&cnt[it], c);
        __syncthreads();
        if (cnt[it] >= KEEP) lo = mid; else hi = mid;
    }
    float T = __uint_as_float(lo);

    // c1 = #{key > T}; need = KEEP - c1 ties at == T must be included.
    {
        int c = (a0 > T) + (a1 > T) + (a2 > T) + (a3 > T)
              + (a4 > T) + (a5 > T) + (a6 > T) + (a7 > T);
        c = __reduce_add_sync(0xFFFFFFFFu, c);
        if ((tid & 31) == 0) atomicAdd(&cnt[NIT], c);
        __syncthreads();
    }
    int need = KEEP - cnt[NIT];

    // Collect exactly KEEP (index, value) pairs.
    #define COLLECT(AV, IDX)                                            \
        {                                                               \
            float av_ = (AV); int i_ = (IDX);                           \
            if (av_ > T) {                                              \
                int slot = atomicAdd(&s_cnt, 1);                        \
                s_idx[slot] = i_; s_val[slot] = sv[i_];                 \
            } else if (av_ == T) {                                      \
                int t_ = atomicAdd(&s_eq, 1);                           \
                if (t_ < need) {                                        \
                    int slot = atomicAdd(&s_cnt, 1);                    \
                    s_idx[slot] = i_; s_val[slot] = sv[i_];             \
                }                                                       \
            }                                                           \
        }
    int base = tid * 4;
    COLLECT(a0, base + 0)
    COLLECT(a1, base + 1)
    COLLECT(a2, base + 2)
    COLLECT(a3, base + 3)
    COLLECT(a4, 1024 + base + 0)
    COLLECT(a5, 1024 + base + 1)
    COLLECT(a6, 1024 + base + 2)
    COLLECT(a7, 1024 + base + 3)
    #undef COLLECT
    __syncthreads();

    if (tid == 0) {
        float z0 = 0.f, z1 = 0.f, z2 = 0.f, z3 = 0.f;
        int j = 0;
        for (; j + 4 <= KEEP; j += 4) {
            z0 += s_val[j]; z1 += s_val[j + 1];
            z2 += s_val[j + 2]; z3 += s_val[j + 3];
        }
        for (; j < KEEP; j++) z0 += s_val[j];
        s_invS = 1.0f / (z0 + z1 + z2 + z3);
    }
    __syncthreads();

    // Sparse reconstruction: thread owns channel c = tid; pool L2-resident.
    float acc = 0.f;
    #pragma unroll 6
    for (int j = 0; j < KEEP; j++) {
        acc = fmaf(s_val[j], __ldg(&pool[(size_t)s_idx[j] * CCH + tid]), acc);
    }
    out[(size_t)n * CCH * LL + (size_t)tid * LL + l] = acc * s_invS;
}

// ---------------------------------------------------------------------------
// Launch
// ---------------------------------------------------------------------------
extern "C" void kernel_launch(void* const* d_in, const int* in_sizes, int n_in,
                              void* d_out, int out_size) {
    const float* x    = (const float*)d_in[0];  // [16, 256, 32, 32]
    const float* pool = (const float*)d_in[1];  // [2048, 256]
    float* out        = (float*)d_out;          // [16, 256, 32, 32]

    prep_pool<<<PP, 256>>>(pool);
    prep_xnorm<<<(NB * LL) / 256, 256>>>(x);
    gemm_cos<<<dim3(PP / BN, LL / BM, NB), 256>>>(x);
    topk_recon<<<NB * LL, 256>>>(pool, out);
}

// round 9
// speedup vs baseline: 1.5244x; 1.3019x over previous
#include <cuda_runtime.h>
#include <cuda_fp16.h>
#include <math.h>
#include <stdint.h>

// Shapes (fixed by the problem)
#define NB   16
#define CCH  256
#define HH   32
#define WW   32
#define LL   (HH*WW)       // 1024
#define PP   2048
#define KEEP 102           // int(0.05 * 2048)
#define K3   768           // 3x fp16 split K (h | l*64 | h/64) . (h | h/64 | l*64)

// ---------------------------------------------------------------------------
// Scratch (device globals only; no allocations allowed)
// ---------------------------------------------------------------------------
__device__ float  g_invxn[NB * LL];                    // 64 KB
__device__ __half g_A[(size_t)NB * LL * K3];           // 25 MB  A' split of x^T * invxn
__device__ __half g_B[(size_t)PP * K3];                // 3 MB   B' split of poolN
__device__ float  g_cos[(size_t)NB * LL * PP];         // 134 MB

// ---------------------------------------------------------------------------
// Kernel 1: normalize pool rows, write fp16 split B' = [h | h/64 | l*64]
// ---------------------------------------------------------------------------
__global__ void prep_pool(const float* __restrict__ pool) {
    int p = blockIdx.x;
    int c = threadIdx.x;
    float v = pool[p * CCH + c];
    __shared__ float red[256];
    red[c] = v * v;
    __syncthreads();
    #pragma unroll
    for (int s = 128; s > 0; s >>= 1) {
        if (c < s) red[c] += red[c + s];
        __syncthreads();
    }
    float vn = v * (1.0f / sqrtf(red[0]));
    __half h  = __float2half(vn);
    float  hf = __half2float(h);
    __half l  = __float2half((vn - hf) * 64.0f);     // scaled residual (normal range)
    __half hs = __float2half(hf * 0.015625f);        // h / 64 (exact pow2 scale)
    __half* dst = g_B + (size_t)p * K3 + c;
    dst[0]   = h;
    dst[256] = hs;
    dst[512] = l;
}

// ---------------------------------------------------------------------------
// Kernel 2: per-pixel inverse norm of x.
// ---------------------------------------------------------------------------
__global__ void prep_xnorm(const float* __restrict__ x) {
    int idx = blockIdx.x * 256 + threadIdx.x;   // 0 .. 16383
    int n = idx >> 10, l = idx & (LL - 1);
    const float* xp = x + (size_t)n * CCH * LL + l;
    float s = 0.f;
    #pragma unroll 8
    for (int c = 0; c < CCH; c++) {
        float v = xp[c * LL];
        s = fmaf(v, v, s);
    }
    g_invxn[idx] = 1.0f / sqrtf(s);
}

// ---------------------------------------------------------------------------
// Kernel 3: transpose x [n][c][l] -> A' [n][l][K3] fp16 split [h | l*64 | h/64],
// with invxn folded in. 32x32 tiles, 256 threads.
// ---------------------------------------------------------------------------
__global__ __launch_bounds__(256) void prep_xT(const float* __restrict__ x) {
    int n  = blockIdx.z;
    int c0 = blockIdx.y * 32;
    int l0 = blockIdx.x * 32;
    int tx = threadIdx.x & 31;
    int ty = threadIdx.x >> 5;     // 0..7
    __shared__ float ss[32][33];

    const float* xp = x + (size_t)n * CCH * LL;
    #pragma unroll
    for (int i = 0; i < 4; i++) {
        int c = ty * 4 + i;
        ss[c][tx] = xp[(size_t)(c0 + c) * LL + l0 + tx];
    }
    __syncthreads();
    #pragma unroll
    for (int i = 0; i < 4; i++) {
        int lloc = ty * 4 + i;
        float s = g_invxn[n * LL + l0 + lloc];
        float v = ss[tx][lloc] * s;
        __half h  = __float2half(v);
        float  hf = __half2float(h);
        __half l  = __float2half((v - hf) * 64.0f);
        __half hs = __float2half(hf * 0.015625f);
        __half* dst = g_A + ((size_t)(n * LL + l0 + lloc)) * K3 + c0 + tx;
        dst[0]   = h;
        dst[256] = l;
        dst[512] = hs;
    }
}

// ---------------------------------------------------------------------------
// Kernel 4: HMMA GEMM via mma.sync.m16n8k16.f32.f16.f16.f32.
// cos[n][l][p] = sum_{k<768} A'[n][l][k] * B'[p][k]
//   = h.h + (l*64).(h/64) + (h/64).(l*64)  ==  fp32-accurate (err ~1e-7)
// CTA tile 128(l) x 128(p), 8 warps in 2x4 (warp tile 64x32),
// BK=64, cp.async double-buffered smem, stride 144 B (conflict-free).
// ---------------------------------------------------------------------------
#define GBK    64
#define NCHUNK (K3 / GBK)          // 12
#define ASTRB  144                 // smem row stride in bytes (72 halves)
#define STAGE_BYTES (128 * ASTRB)  // 18432 per operand
#define SM_A_OFF(s) ((s) * 2 * STAGE_BYTES)
#define SM_B_OFF(s) ((s) * 2 * STAGE_BYTES + STAGE_BYTES)
#define SMEM_GEMM  (4 * STAGE_BYTES)   // 73728

__device__ __forceinline__ uint32_t smem_u32(const void* p) {
    uint32_t a;
    asm("{ .reg .u64 t; cvta.to.shared.u64 t, %1; cvt.u32.u64 %0, t; }" : "=r"(a) : "l"(p));
    return a;
}
#define CP16(sm_addr, gptr) \
    asm volatile("cp.async.cg.shared.global [%0], [%1], 16;" :: "r"(sm_addr), "l"(gptr) : "memory")
#define CP_COMMIT() asm volatile("cp.async.commit_group;" ::: "memory")
#define CP_WAIT(N)  asm volatile("cp.async.wait_group %0;" :: "n"(N) : "memory")

__device__ __forceinline__ void mma_fp16(float* c, const uint32_t* a, const uint32_t* b) {
    asm volatile(
        "mma.sync.aligned.m16n8k16.row.col.f32.f16.f16.f32 "
        "{%0,%1,%2,%3}, {%4,%5,%6,%7}, {%8,%9}, {%0,%1,%2,%3};"
        : "+f"(c[0]), "+f"(c[1]), "+f"(c[2]), "+f"(c[3])
        : "r"(a[0]), "r"(a[1]), "r"(a[2]), "r"(a[3]), "r"(b[0]), "r"(b[1]));
}

__global__ __launch_bounds__(256, 1) void gemm_mma() {
    extern __shared__ __align__(1024) char sm[];
    uint32_t smb = smem_u32(sm);

    int tid  = threadIdx.x;
    int lane = tid & 31;
    int warp = tid >> 5;
    int wm   = warp & 1;        // 0..1  (M half, 64 rows)
    int wn   = warp >> 1;       // 0..3  (N quarter, 32 cols)

    int n    = blockIdx.z;
    int pBlk = blockIdx.x * 128;
    int lBlk = blockIdx.y * 128;

    const __half* Ag = g_A + ((size_t)(n * LL + lBlk)) * K3;
    const __half* Bg = g_B + (size_t)pBlk * K3;

    // loader: 128 rows x 64 halves (8 x 16B segs per row) per operand.
    #define LOADCHUNK(KC, S)                                                     \
    {                                                                            \
        int kc_ = (KC);                                                          \
        uint32_t sa = smb + SM_A_OFF(S);                                         \
        uint32_t sb = smb + SM_B_OFF(S);                                         \
        _Pragma("unroll")                                                        \
        for (int j = 0; j < 4; j++) {                                            \
            int u = tid + j * 256;                                               \
            int row = u >> 3, seg = u & 7;                                       \
            CP16(sa + row * ASTRB + seg * 16,                                    \
                 Ag + (size_t)row * K3 + kc_ * GBK + seg * 8);                   \
        }                                                                        \
        _Pragma("unroll")                                                        \
        for (int j = 0; j < 4; j++) {                                            \
            int u = tid + j * 256;                                               \
            int row = u >> 3, seg = u & 7;                                       \
            CP16(sb + row * ASTRB + seg * 16,                                    \
                 Bg + (size_t)row * K3 + kc_ * GBK + seg * 8);                   \
        }                                                                        \
    }

    float acc[4][4][4];
    #pragma unroll
    for (int i = 0; i < 4; i++)
        #pragma unroll
        for (int j = 0; j < 4; j++)
            #pragma unroll
            for (int q = 0; q < 4; q++) acc[i][j][q] = 0.f;

    int r  = lane >> 2;        // 0..7
    int cq = lane & 3;         // 0..3

    LOADCHUNK(0, 0);
    CP_COMMIT();

    #pragma unroll 1
    for (int kc = 0; kc < NCHUNK; kc++) {
        if (kc < NCHUNK - 1) {
            LOADCHUNK(kc + 1, (kc + 1) & 1);
            CP_COMMIT();
            CP_WAIT(1);
        } else {
            CP_WAIT(0);
        }
        __syncthreads();

        const char* As = sm + SM_A_OFF(kc & 1);
        const char* Bs = sm + SM_B_OFF(kc & 1);

        #pragma unroll
        for (int ks = 0; ks < GBK / 16; ks++) {
            int kb = ks * 32 + cq * 4;      // byte offset of this thread's k-pair
            uint32_t a[4][4], b[4][2];
            #pragma unroll
            for (int mt = 0; mt < 4; mt++) {
                const char* base = As + (wm * 64 + mt * 16 + r) * ASTRB + kb;
                a[mt][0] = *(const uint32_t*)(base);
                a[mt][1] = *(const uint32_t*)(base + 8 * ASTRB);
                a[mt][2] = *(const uint32_t*)(base + 16);
                a[mt][3] = *(const uint32_t*)(base + 8 * ASTRB + 16);
            }
            #pragma unroll
            for (int nt = 0; nt < 4; nt++) {
                const char* base = Bs + (wn * 32 + nt * 8 + r) * ASTRB + kb;
                b[nt][0] = *(const uint32_t*)(base);
                b[nt][1] = *(const uint32_t*)(base + 16);
            }
            #pragma unroll
            for (int mt = 0; mt < 4; mt++)
                #pragma unroll
                for (int nt = 0; nt < 4; nt++)
                    mma_fp16(acc[mt][nt], a[mt], b[nt]);
        }
        __syncthreads();
    }

    // Epilogue: write g_cos[n][l][p]
    #pragma unroll
    for (int mt = 0; mt < 4; mt++) {
        int l0 = lBlk + wm * 64 + mt * 16 + r;
        float* row0 = g_cos + ((size_t)(n * LL + l0)) * PP + pBlk;
        float* row1 = g_cos + ((size_t)(n * LL + l0 + 8)) * PP + pBlk;
        #pragma unroll
        for (int nt = 0; nt < 4; nt++) {
            int p = wn * 32 + nt * 8 + cq * 2;
            float2 v0 = make_float2(acc[mt][nt][0], acc[mt][nt][1]);
            float2 v1 = make_float2(acc[mt][nt][2], acc[mt][nt][3]);
            *(float2*)&row0[p] = v0;
            *(float2*)&row1[p] = v1;
        }
    }
}

// ---------------------------------------------------------------------------
// Kernel 5: per-pixel exact top-102 (atomic-free binary search) + sparse recon.
// ---------------------------------------------------------------------------
#define NIT 30

__global__ __launch_bounds__(256) void topk_recon(const float* __restrict__ pool,
                                                  float* __restrict__ out) {
    int blk = blockIdx.x;            // n*1024 + l
    int n = blk >> 10, l = blk & (LL - 1);
    const float* row = g_cos + (size_t)blk * PP;

    __shared__ float sv[PP];
    __shared__ int   cnt[NIT + 2];
    __shared__ int   s_cnt, s_eq;
    __shared__ int   s_idx[KEEP];
    __shared__ float s_val[KEEP];
    __shared__ float s_invS;

    int tid = threadIdx.x;

    float4 r0 = *(const float4*)&row[tid * 4];
    float4 r1 = *(const float4*)&row[1024 + tid * 4];
    *(float4*)&sv[tid * 4]        = r0;
    *(float4*)&sv[1024 + tid * 4] = r1;

    float a0 = fabsf(r0.x), a1 = fabsf(r0.y), a2 = fabsf(r0.z), a3 = fabsf(r0.w);
    float a4 = fabsf(r1.x), a5 = fabsf(r1.y), a6 = fabsf(r1.z), a7 = fabsf(r1.w);

    if (tid < NIT + 2) cnt[tid] = 0;
    if (tid == 0) { s_cnt = 0; s_eq = 0; }
    __syncthreads();

    unsigned lo = 0u, hi = 0x3FC00000u;
    #pragma unroll 1
    for (int it = 0; it < NIT; it++) {
        unsigned mid = (lo + hi) >> 1;
        float mf = __uint_as_float(mid);
        int c = (a0 >= mf) + (a1 >= mf) + (a2 >= mf) + (a3 >= mf)
              + (a4 >= mf) + (a5 >= mf) + (a6 >= mf) + (a7 >= mf);
        c = __reduce_add_sync(0xFFFFFFFFu, c);
        if ((tid & 31) == 0) atomicAdd(&cnt[it], c);
        __syncthreads();
        if (cnt[it] >= KEEP) lo = mid; else hi = mid;
    }
    float T = __uint_as_float(lo);

    {
        int c = (a0 > T) + (a1 > T) + (a2 > T) + (a3 > T)
              + (a4 > T) + (a5 > T) + (a6 > T) + (a7 > T);
        c = __reduce_add_sync(0xFFFFFFFFu, c);
        if ((tid & 31) == 0) atomicAdd(&cnt[NIT], c);
        __syncthreads();
    }
    int need = KEEP - cnt[NIT];

    #define COLLECT(AV, IDX)                                            \
        {                                                               \
            float av_ = (AV); int i_ = (IDX);                           \
            if (av_ > T) {                                              \
                int slot = atomicAdd(&s_cnt, 1);                        \
                s_idx[slot] = i_; s_val[slot] = sv[i_];                 \
            } else if (av_ == T) {                                      \
                int t_ = atomicAdd(&s_eq, 1);                           \
                if (t_ < need) {                                        \
                    int slot = atomicAdd(&s_cnt, 1);                    \
                    s_idx[slot] = i_; s_val[slot] = sv[i_];             \
                }                                                       \
            }                                                           \
        }
    int base = tid * 4;
    COLLECT(a0, base + 0)
    COLLECT(a1, base + 1)
    COLLECT(a2, base + 2)
    COLLECT(a3, base + 3)
    COLLECT(a4, 1024 + base + 0)
    COLLECT(a5, 1024 + base + 1)
    COLLECT(a6, 1024 + base + 2)
    COLLECT(a7, 1024 + base + 3)
    #undef COLLECT
    __syncthreads();

    if (tid == 0) {
        float z0 = 0.f, z1 = 0.f, z2 = 0.f, z3 = 0.f;
        int j = 0;
        for (; j + 4 <= KEEP; j += 4) {
            z0 += s_val[j]; z1 += s_val[j + 1];
            z2 += s_val[j + 2]; z3 += s_val[j + 3];
        }
        for (; j < KEEP; j++) z0 += s_val[j];
        s_invS = 1.0f / (z0 + z1 + z2 + z3);
    }
    __syncthreads();

    float acc = 0.f;
    #pragma unroll 6
    for (int j = 0; j < KEEP; j++) {
        acc = fmaf(s_val[j], __ldg(&pool[(size_t)s_idx[j] * CCH + tid]), acc);
    }
    out[(size_t)n * CCH * LL + (size_t)tid * LL + l] = acc * s_invS;
}

// ---------------------------------------------------------------------------
// Launch
// ---------------------------------------------------------------------------
extern "C" void kernel_launch(void* const* d_in, const int* in_sizes, int n_in,
                              void* d_out, int out_size) {
    const float* x    = (const float*)d_in[0];  // [16, 256, 32, 32]
    const float* pool = (const float*)d_in[1];  // [2048, 256]
    float* out        = (float*)d_out;          // [16, 256, 32, 32]

    cudaFuncSetAttribute(gemm_mma, cudaFuncAttributeMaxDynamicSharedMemorySize, SMEM_GEMM);

    prep_pool<<<PP, 256>>>(pool);
    prep_xnorm<<<(NB * LL) / 256, 256>>>(x);
    prep_xT<<<dim3(LL / 32, CCH / 32, NB), 256>>>(x);
    gemm_mma<<<dim3(PP / 128, LL / 128, NB), 256, SMEM_GEMM>>>();
    topk_recon<<<NB * LL, 256>>>(pool, out);
}